// round 1
// baseline (speedup 1.0000x reference)
#include <cuda_runtime.h>
#include <cuda_bf16.h>
#include <math.h>

// Problem constants
#define NB 256
#define CC 256
#define TT 64
#define VV 25
#define ROWF (TT*VV)          // 1600 floats per (n,c)
#define CHUNK 8               // channels staged per iteration
#define STAGEF (CHUNK*ROWF)   // 12800 floats
#define NCHUNK (CC/CHUNK)     // 32
#define THREADS 512
#define NSWEEP 10

// Shared memory layout (floats)
#define OFF_STAGE 0
#define OFF_XM    (OFF_STAGE + STAGEF)        // 12800
#define OFF_MU    (OFF_XM + CC*VV)            // 19200 (6400)
#define OFF_S     (OFF_MU + 32)               // 19232
#define OFF_MW    (OFF_S + 640)               // 19872
#define OFF_P     (OFF_MW + 256)              // 20128
#define OFF_A     (OFF_P + 256)               // 20384
#define OFF_U     (OFF_A + 128)               // 20512
#define OFF_L     (OFF_U + 128)               // 20640
#define OFF_LW    (OFF_L + 128)               // 20768
#define SMEM_FLOATS (OFF_LW + 16)             // 20784
#define SMEM_BYTES (SMEM_FLOATS * 4)          // 83136

__device__ float d_M[256];   // composite projection M = W1*W2*W3 (25x10)

// ---------------------------------------------------------------------------
// Tiny kernel: M = W1 (25x20) @ W2 (20x15) @ W3 (15x10)
// ---------------------------------------------------------------------------
__global__ void buildM_kernel(const float* __restrict__ W1,
                              const float* __restrict__ W2,
                              const float* __restrict__ W3) {
    __shared__ float t1[25 * 15];
    int tid = threadIdx.x;
    if (tid < 375) {
        int i = tid / 15, j = tid - 15 * i;
        float a = 0.f;
        #pragma unroll
        for (int k = 0; k < 20; k++) a += W1[i * 20 + k] * W2[k * 15 + j];
        t1[i * 15 + j] = a;
    }
    __syncthreads();
    if (tid < 250) {
        int i = tid / 10, j = tid - 10 * i;
        float a = 0.f;
        #pragma unroll
        for (int k = 0; k < 15; k++) a += t1[i * 15 + k] * W3[k * 10 + j];
        d_M[i * 10 + j] = a;
    }
}

// ---------------------------------------------------------------------------
// Fused kernel: one block per batch element n.
//   1. stream x[n] (1.6MB) through shared, compute xm[c][v] = mean_t
//   2. mu[v] = sum_c xm ; S = sum_c xm xm^T ; cov = (S - mu mu^T/C)/(C-1)+eps I
//   3. G = M^T cov M  (10x10 SPD)
//   4. LogEig via parallel-order cyclic Jacobi
//   5. out[n] = vec(L) @ fc_w^T + fc_b
// ---------------------------------------------------------------------------
__global__ __launch_bounds__(THREADS, 2)
void fused_spdnet_kernel(const float* __restrict__ x,
                         const float* __restrict__ fc_w,
                         const float* __restrict__ fc_b,
                         float* __restrict__ out) {
    extern __shared__ float sm[];
    float* stage = sm + OFF_STAGE;
    float* xm    = sm + OFF_XM;
    float* mu    = sm + OFF_MU;
    float* S     = sm + OFF_S;
    float* Mw    = sm + OFF_MW;
    float* P     = sm + OFF_P;
    float* A     = sm + OFF_A;
    float* U     = sm + OFF_U;
    float* Lm    = sm + OFF_L;
    float* lw    = sm + OFF_LW;

    const int tid = threadIdx.x;
    const int n = blockIdx.x;

    if (tid < 32) mu[tid] = 0.f;
    for (int i = tid; i < 250; i += THREADS) Mw[i] = d_M[i];

    // ---- Phase 1: per-channel temporal mean -------------------------------
    const float4* src4 = (const float4*)(x + (size_t)n * (CC * ROWF));
    float mu_part = 0.f;
    int cl = 0, v = 0;
    const bool red_act = (tid < CHUNK * VV);  // 200 reducer threads
    if (red_act) { cl = tid / VV; v = tid - VV * cl; }

    for (int ch = 0; ch < NCHUNK; ch++) {
        __syncthreads();  // protect previous chunk's stage reads (and mu init)
        const float4* s4 = src4 + (size_t)ch * (STAGEF / 4);
        float4* st4 = (float4*)stage;
        #pragma unroll
        for (int i = tid; i < STAGEF / 4; i += THREADS) st4[i] = s4[i];
        __syncthreads();
        if (red_act) {
            const float* base = stage + cl * ROWF + v;
            float a0 = 0.f, a1 = 0.f;
            #pragma unroll
            for (int t = 0; t < TT; t += 2) {
                a0 += base[t * VV];
                a1 += base[(t + 1) * VV];
            }
            float m = (a0 + a1) * (1.f / (float)TT);
            xm[(ch * CHUNK + cl) * VV + v] = m;
            mu_part += m;
        }
    }
    if (red_act) atomicAdd(&mu[v], mu_part);
    __syncthreads();

    // ---- Phase 2: covariance (upper triangle, 325 entries) ----------------
    if (tid < 325) {
        int i = 0, rem = tid;
        while (rem >= VV - i) { rem -= VV - i; i++; }
        int j = i + rem;
        const float* xi = xm + i;
        const float* xj = xm + j;
        float a0 = 0.f, a1 = 0.f;
        #pragma unroll 8
        for (int c = 0; c < CC; c += 2) {
            a0 += xi[c * VV] * xj[c * VV];
            a1 += xi[(c + 1) * VV] * xj[(c + 1) * VV];
        }
        float Sij = a0 + a1;
        float cv = (Sij - mu[i] * mu[j] * (1.f / (float)CC)) * (1.f / (float)(CC - 1));
        if (i == j) cv += 1e-8f;
        S[i * VV + j] = cv;
        S[j * VV + i] = cv;
    }
    __syncthreads();

    // ---- Phase 3: G = M^T cov M  (10x10) ----------------------------------
    if (tid < 250) {
        int i = tid / 10, l = tid - 10 * i;
        float a = 0.f;
        #pragma unroll
        for (int k = 0; k < VV; k++) a += S[i * VV + k] * Mw[k * 10 + l];
        P[tid] = a;
    }
    __syncthreads();
    if (tid < 100) {
        int l = tid / 10, m = tid - 10 * l;
        float a = 0.f;
        #pragma unroll
        for (int k = 0; k < VV; k++) a += Mw[k * 10 + l] * P[k * 10 + m];
        Lm[tid] = a;   // temp (possibly slightly asymmetric)
    }
    __syncthreads();
    if (tid < 100) {
        int l = tid / 10, m = tid - 10 * l;
        A[tid] = 0.5f * (Lm[l * 10 + m] + Lm[m * 10 + l]);
        U[tid] = (l == m) ? 1.f : 0.f;
    }
    __syncthreads();

    // ---- Phase 4: Jacobi eigensolver, parallel (round-robin) ordering -----
    // 5 disjoint rotations per round, 9 rounds per sweep, NSWEEP sweeps.
    for (int sweep = 0; sweep < NSWEEP; sweep++) {
        for (int r = 0; r < 9; r++) {
            float c = 1.f, s = 0.f, akp = 0.f, akq = 0.f, ukp = 0.f, ukq = 0.f;
            int p = 0, q = 1, k = 0;
            const bool act = (tid < 50);
            if (act) {
                int pj = tid / 10; k = tid - 10 * pj;
                int a1 = (pj == 0) ? 0 : ((pj - 1 + r) % 9) + 1;
                int a2 = ((8 - pj + r) % 9) + 1;
                p = min(a1, a2);
                q = max(a1, a2);
                float apq = A[p * 10 + q];
                float app = A[p * 10 + p];
                float aqq = A[q * 10 + q];
                if (fabsf(apq) > 1e-20f) {
                    float tau = (aqq - app) / (2.f * apq);
                    float tt = 1.f / (fabsf(tau) + sqrtf(1.f + tau * tau));
                    if (tau < 0.f) tt = -tt;
                    c = rsqrtf(1.f + tt * tt);
                    s = tt * c;
                }
                akp = A[k * 10 + p]; akq = A[k * 10 + q];
                ukp = U[k * 10 + p]; ukq = U[k * 10 + q];
            }
            __syncthreads();  // all reads (angles + col values) before writes
            if (act) {
                A[k * 10 + p] = c * akp - s * akq;
                A[k * 10 + q] = s * akp + c * akq;
                U[k * 10 + p] = c * ukp - s * ukq;
                U[k * 10 + q] = s * ukp + c * ukq;
            }
            __syncthreads();  // column phase done before row phase
            if (act) {
                float apk = A[p * 10 + k], aqk = A[q * 10 + k];
                A[p * 10 + k] = c * apk - s * aqk;
                A[q * 10 + k] = s * apk + c * aqk;
            }
            __syncthreads();  // round complete
        }
    }

    // ---- Phase 5: LogEig reconstruct L = U diag(log w) U^T ----------------
    if (tid < 10) lw[tid] = logf(fmaxf(A[tid * 10 + tid], 1e-30f));
    __syncthreads();
    if (tid < 100) {
        int i = tid / 10, j = tid - 10 * i;
        float a = 0.f;
        #pragma unroll
        for (int l = 0; l < 10; l++) a += U[i * 10 + l] * lw[l] * U[j * 10 + l];
        Lm[tid] = a;
    }
    __syncthreads();

    // ---- Phase 6: FC  out[n,o] = vec(L) . fc_w[o,:] + fc_b[o] -------------
    if (tid < 64) {
        float a = fc_b[tid];
        const float* wr = fc_w + tid * 100;
        #pragma unroll
        for (int f = 0; f < 100; f++) a += Lm[f] * wr[f];
        out[(size_t)n * 64 + tid] = a;
    }
}

extern "C" void kernel_launch(void* const* d_in, const int* in_sizes, int n_in,
                              void* d_out, int out_size) {
    const float* x    = (const float*)d_in[0];
    const float* W1   = (const float*)d_in[1];
    const float* W2   = (const float*)d_in[2];
    const float* W3   = (const float*)d_in[3];
    const float* fc_w = (const float*)d_in[4];
    const float* fc_b = (const float*)d_in[5];
    float* out = (float*)d_out;

    cudaFuncSetAttribute(fused_spdnet_kernel,
                         cudaFuncAttributeMaxDynamicSharedMemorySize, SMEM_BYTES);

    buildM_kernel<<<1, 512>>>(W1, W2, W3);
    fused_spdnet_kernel<<<NB, THREADS, SMEM_BYTES>>>(x, fc_w, fc_b, out);
}

// round 9
// speedup vs baseline: 1.0598x; 1.0598x over previous
#include <cuda_runtime.h>
#include <cuda_bf16.h>
#include <math.h>

#define NB 256
#define CC 256
#define TT 64
#define VV 25
#define ROWF (TT*VV)          // 1600 floats per (n,c) row
#define NROWS (NB*CC)         // 65536
#define WARPS_PER_BLK_A 8
#define THREADS_A (WARPS_PER_BLK_A*32)
#define BLOCKS_A (NROWS/WARPS_PER_BLK_A)
#define THREADS_B 352
#define NSWEEP 8

__device__ float d_xm[NROWS * VV];   // per-(n,c) temporal means: 6.4 MB scratch

// ---------------------------------------------------------------------------
// Kernel A: streaming temporal mean. One warp per (n,c) row.
// Row = 1600 floats = 16 groups of 100 floats (100 floats = 4 timesteps).
// Lane j<25 sums float4 at phase j across the 16 groups (coalesced LDG.128,
// MLP=16); a 100-float warp-shared un-permute then folds the 4 t-phases per v.
// ---------------------------------------------------------------------------
__global__ __launch_bounds__(THREADS_A)
void mean_kernel(const float* __restrict__ x) {
    __shared__ float sh[WARPS_PER_BLK_A][100];
    const int warp = threadIdx.x >> 5;
    const int lane = threadIdx.x & 31;
    const int r = blockIdx.x * WARPS_PER_BLK_A + warp;   // row id in [0, 65536)

    const float4* src = (const float4*)(x + (size_t)r * ROWF);
    if (lane < 25) {
        float4 acc = make_float4(0.f, 0.f, 0.f, 0.f);
        #pragma unroll
        for (int g = 0; g < 16; g++) {
            float4 v = __ldcs(src + lane + 25 * g);   // streaming: no reuse
            acc.x += v.x; acc.y += v.y; acc.z += v.z; acc.w += v.w;
        }
        ((float4*)sh[warp])[lane] = acc;
    }
    __syncwarp();
    if (lane < 25) {
        // flat position p within 100-group maps to v = p % 25; fold 4 phases
        float s = sh[warp][lane] + sh[warp][lane + 25]
                + sh[warp][lane + 50] + sh[warp][lane + 75];
        d_xm[(size_t)r * VV + lane] = s * (1.f / (float)TT);
    }
}

// ---------------------------------------------------------------------------
// Kernel B: per-n tail. Block per batch element, 352 threads.
//  M = W1 W2 W3; mu; covariance; G = M^T cov M; Jacobi LogEig; FC.
// ---------------------------------------------------------------------------
__global__ __launch_bounds__(THREADS_B)
void spd_tail_kernel(const float* __restrict__ W1,
                     const float* __restrict__ W2,
                     const float* __restrict__ W3,
                     const float* __restrict__ fc_w,
                     const float* __restrict__ fc_b,
                     float* __restrict__ out) {
    __shared__ float xm[CC * VV];      // 6400
    __shared__ float t1[384];          // W1*W2 (25x15)
    __shared__ float Mw[256];          // M (25x10)
    __shared__ float mu[32];
    __shared__ float S[VV * VV + 15];  // cov 25x25
    __shared__ float P[256];           // cov*M (25x10)
    __shared__ float Am[128];          // working 10x10
    __shared__ float U[128];
    __shared__ float Lm[128];
    __shared__ float lw[16];

    const int tid = threadIdx.x;
    const int n = blockIdx.x;

    // ---- load xm for this n (1600 float4) + build t1 = W1*W2 --------------
    const float4* src4 = (const float4*)(d_xm + (size_t)n * CC * VV);
    #pragma unroll
    for (int i = tid; i < CC * VV / 4; i += THREADS_B)
        ((float4*)xm)[i] = src4[i];
    for (int i = tid; i < 375; i += THREADS_B) {
        int r = i / 15, j = i - 15 * r;
        float a = 0.f;
        #pragma unroll
        for (int k = 0; k < 20; k++) a += W1[r * 20 + k] * W2[k * 15 + j];
        t1[i] = a;
    }
    __syncthreads();

    // ---- M = t1*W3 ; mu[v] = sum_c xm[c][v] -------------------------------
    for (int i = tid; i < 250; i += THREADS_B) {
        int r = i / 10, j = i - 10 * r;
        float a = 0.f;
        #pragma unroll
        for (int k = 0; k < 15; k++) a += t1[r * 15 + k] * W3[k * 10 + j];
        Mw[i] = a;
    }
    if (tid < VV) {
        float s = 0.f;
        #pragma unroll 8
        for (int c = 0; c < CC; c++) s += xm[c * VV + tid];
        mu[tid] = s;
    }
    __syncthreads();

    // ---- covariance upper triangle (325 pairs) ----------------------------
    if (tid < 325) {
        int i = 0, rem = tid;
        while (rem >= VV - i) { rem -= VV - i; i++; }
        int j = i + rem;
        const float* xi = xm + i;
        const float* xj = xm + j;
        float a0 = 0.f, a1 = 0.f;
        #pragma unroll 8
        for (int c = 0; c < CC; c += 2) {
            a0 += xi[c * VV] * xj[c * VV];
            a1 += xi[(c + 1) * VV] * xj[(c + 1) * VV];
        }
        float cv = (a0 + a1 - mu[i] * mu[j] * (1.f / (float)CC)) * (1.f / (float)(CC - 1));
        if (i == j) cv += 1e-8f;
        S[i * VV + j] = cv;
        S[j * VV + i] = cv;
    }
    __syncthreads();

    // ---- P = cov * M (25x10) ----------------------------------------------
    if (tid < 250) {
        int i = tid / 10, l = tid - 10 * i;
        float a = 0.f;
        #pragma unroll
        for (int k = 0; k < VV; k++) a += S[i * VV + k] * Mw[k * 10 + l];
        P[tid] = a;
    }
    __syncthreads();
    // ---- G = M^T * P (10x10), symmetrized ---------------------------------
    if (tid < 100) {
        int l = tid / 10, m = tid - 10 * l;
        float a = 0.f;
        #pragma unroll
        for (int k = 0; k < VV; k++) a += Mw[k * 10 + l] * P[k * 10 + m];
        Lm[tid] = a;
    }
    __syncthreads();
    if (tid < 100) {
        int l = tid / 10, m = tid - 10 * l;
        Am[tid] = 0.5f * (Lm[l * 10 + m] + Lm[m * 10 + l]);
        U[tid] = (l == m) ? 1.f : 0.f;
    }
    __syncthreads();

    // ---- Jacobi eigensolver, parallel round-robin ordering ----------------
    for (int sweep = 0; sweep < NSWEEP; sweep++) {
        for (int r = 0; r < 9; r++) {
            float c = 1.f, s = 0.f, akp = 0.f, akq = 0.f, ukp = 0.f, ukq = 0.f;
            int p = 0, q = 1, k = 0;
            const bool act = (tid < 50);
            if (act) {
                int pj = tid / 10; k = tid - 10 * pj;
                int a1 = (pj == 0) ? 0 : ((pj - 1 + r) % 9) + 1;
                int a2 = ((8 - pj + r) % 9) + 1;
                p = min(a1, a2);
                q = max(a1, a2);
                float apq = Am[p * 10 + q];
                float app = Am[p * 10 + p];
                float aqq = Am[q * 10 + q];
                if (fabsf(apq) > 1e-20f) {
                    float tau = (aqq - app) / (2.f * apq);
                    float tt = 1.f / (fabsf(tau) + sqrtf(1.f + tau * tau));
                    if (tau < 0.f) tt = -tt;
                    c = rsqrtf(1.f + tt * tt);
                    s = tt * c;
                }
                akp = Am[k * 10 + p]; akq = Am[k * 10 + q];
                ukp = U[k * 10 + p];  ukq = U[k * 10 + q];
            }
            __syncthreads();
            if (act) {
                Am[k * 10 + p] = c * akp - s * akq;
                Am[k * 10 + q] = s * akp + c * akq;
                U[k * 10 + p] = c * ukp - s * ukq;
                U[k * 10 + q] = s * ukp + c * ukq;
            }
            __syncthreads();
            if (act) {
                float apk = Am[p * 10 + k], aqk = Am[q * 10 + k];
                Am[p * 10 + k] = c * apk - s * aqk;
                Am[q * 10 + k] = s * apk + c * aqk;
            }
            __syncthreads();
        }
    }

    // ---- LogEig reconstruct + FC ------------------------------------------
    if (tid < 10) lw[tid] = logf(fmaxf(Am[tid * 10 + tid], 1e-30f));
    __syncthreads();
    if (tid < 100) {
        int i = tid / 10, j = tid - 10 * i;
        float a = 0.f;
        #pragma unroll
        for (int l = 0; l < 10; l++) a += U[i * 10 + l] * lw[l] * U[j * 10 + l];
        Lm[tid] = a;
    }
    __syncthreads();
    if (tid < 64) {
        float a = fc_b[tid];
        const float* wr = fc_w + tid * 100;
        #pragma unroll
        for (int f = 0; f < 100; f++) a += Lm[f] * wr[f];
        out[(size_t)n * 64 + tid] = a;
    }
}

extern "C" void kernel_launch(void* const* d_in, const int* in_sizes, int n_in,
                              void* d_out, int out_size) {
    const float* x    = (const float*)d_in[0];
    const float* W1   = (const float*)d_in[1];
    const float* W2   = (const float*)d_in[2];
    const float* W3   = (const float*)d_in[3];
    const float* fc_w = (const float*)d_in[4];
    const float* fc_b = (const float*)d_in[5];
    float* out = (float*)d_out;

    mean_kernel<<<BLOCKS_A, THREADS_A>>>(x);
    spd_tail_kernel<<<NB, THREADS_B>>>(W1, W2, W3, fc_w, fc_b, out);
}